// round 5
// baseline (speedup 1.0000x reference)
#include <cuda_runtime.h>

#define NMAX      16384
#define TPB       256
#define RPT       8                    // rows per thread
#define ROWS_BLK  (TPB * RPT)          // 2048 rows per block
#define TILE      128                  // columns staged in smem per tile
#define YCHUNKS   74                   // 8 x 74 = 592 blocks = 148 SMs x 4 resident
#define FIN_BLKS  64

__device__ float g_minA[NMAX];   // per pred row i: min_j 0.5*d2(i,j)
__device__ float g_minB[NMAX];   // per gt  col j: min_i 0.5*d2(i,j)
__device__ float g_part[FIN_BLKS];

__device__ __forceinline__ float inf_f() { return __int_as_float(0x7f800000); }

// Mixed-sign atomic float min (global or shared): positives via signed
// int-min, negatives via uint-max. Init sentinel: big positive float
// (0x7F7F7F7F = 3.39e38 from the memset).
__device__ __forceinline__ void atomicMinF(float* addr, float val) {
    if (val >= 0.0f) atomicMin((int*)addr, __float_as_int(val));
    else             atomicMax((unsigned int*)addr, __float_as_uint(val));
}

// Single sweep of the implicit 16384x16384 half-squared-distance matrix:
//   w_ij = 0.5*d2(i,j) = (h_i + c_j) - x_i.y_j
// Row mins accumulate in registers across the block's column chunk; col mins
// via 8-deep register tree + 5-shfl warp reduce + smem tile atomics.
__global__ void __launch_bounds__(TPB, 4)
pass_kernel(const float* __restrict__ P, const float* __restrict__ G,
            int NP, int NG) {
    __shared__ float4 sy[TILE];
    __shared__ float  colminS[TILE];

    const int tid  = threadIdx.x;
    const int lane = tid & 31;
    const int row0 = blockIdx.x * ROWS_BLK + tid;

    float nx0[RPT], nx1[RPT], nx2[RPT], h[RPT], rowmin[RPT];
#pragma unroll
    for (int p = 0; p < RPT; p++) {
        int r = row0 + p * TPB;
        if (r < NP) {
            float a = P[3*r], b = P[3*r+1], c = P[3*r+2];
            nx0[p] = -a; nx1[p] = -b; nx2[p] = -c;
            h[p] = 0.5f * (a*a + b*b + c*c);
        } else {
            nx0[p] = 0.f; nx1[p] = 0.f; nx2[p] = 0.f;
            h[p] = inf_f();              // invalid row -> w = +INF, never wins colmin
        }
        rowmin[p] = inf_f();
    }

    const int chunk = (NG + YCHUNKS - 1) / YCHUNKS;
    const int yb = blockIdx.y * chunk;
    const int ye = min(yb + chunk, NG);

    for (int t0 = yb; t0 < ye; t0 += TILE) {
        const int tn = min(TILE, ye - t0);
        __syncthreads();
        for (int j = tid; j < tn; j += TPB) {
            int g = t0 + j;
            float a = G[3*g], b = G[3*g+1], c = G[3*g+2];
            sy[j] = make_float4(a, b, c, 0.5f * (a*a + b*b + c*c));
            colminS[j] = inf_f();
        }
        __syncthreads();

#pragma unroll 2
        for (int j = 0; j < tn; j++) {
            const float4 y = sy[j];               // one LDS.128, broadcast
            float cm;
#pragma unroll
            for (int p = 0; p < RPT; p++) {
                float w = h[p] + y.w;             // h_i + c_j
                w = fmaf(nx2[p], y.z, w);
                w = fmaf(nx1[p], y.y, w);
                w = fmaf(nx0[p], y.x, w);         // = 0.5*d2
                rowmin[p] = fminf(rowmin[p], w);
                cm = (p == 0) ? w : fminf(cm, w);
            }
#pragma unroll
            for (int o = 16; o > 0; o >>= 1)
                cm = fminf(cm, __shfl_down_sync(0xffffffffu, cm, o));
            if (lane == 0) atomicMinF(&colminS[j], cm);
        }

        __syncthreads();
        for (int j = tid; j < tn; j += TPB)
            atomicMinF(&g_minB[t0 + j], colminS[j]);
    }

#pragma unroll
    for (int p = 0; p < RPT; p++) {
        int r = row0 + p * TPB;
        if (r < NP) atomicMinF(&g_minA[r], rowmin[p]);
    }
}

// Stage 1: FIN_BLKS blocks reduce slices of both min arrays to g_part.
__global__ void finalize1_kernel(int NP, int NG) {
    __shared__ float ssum[32];
    const int tid = threadIdx.x;
    const int gid = blockIdx.x * blockDim.x + tid;
    const int stride = gridDim.x * blockDim.x;
    const float wP = 1.0f / (float)NP;
    const float wG = 1.0f / (float)NG;
    float acc = 0.f;

    for (int i = gid; i < NP; i += stride)
        acc += sqrtf(fmaxf(2.0f * g_minA[i], 0.f)) * wP;
    for (int j = gid; j < NG; j += stride)
        acc += sqrtf(fmaxf(2.0f * g_minB[j], 0.f)) * wG;

#pragma unroll
    for (int o = 16; o > 0; o >>= 1) acc += __shfl_down_sync(0xffffffffu, acc, o);
    if ((tid & 31) == 0) ssum[tid >> 5] = acc;
    __syncthreads();
    if (tid < 32) {
        int nwarps = blockDim.x >> 5;
        float v = (tid < nwarps) ? ssum[tid] : 0.f;
#pragma unroll
        for (int o = 16; o > 0; o >>= 1) v += __shfl_down_sync(0xffffffffu, v, o);
        if (tid == 0) g_part[blockIdx.x] = v;
    }
}

// Stage 2: one warp, fixed-order sum of the partials (deterministic).
__global__ void finalize2_kernel(float* __restrict__ out) {
    const int tid = threadIdx.x;
    float v = (tid < FIN_BLKS) ? g_part[tid] : 0.f;
    if (tid + 32 < FIN_BLKS) v += g_part[tid + 32];
#pragma unroll
    for (int o = 16; o > 0; o >>= 1) v += __shfl_down_sync(0xffffffffu, v, o);
    if (tid == 0) out[0] = v;
}

extern "C" void kernel_launch(void* const* d_in, const int* in_sizes, int n_in,
                              void* d_out, int out_size) {
    const float* P = (const float*)d_in[0];
    const float* G = (const float*)d_in[1];
    const int NP = in_sizes[0] / 3;
    const int NG = in_sizes[1] / 3;
    float* out = (float*)d_out;

    // Sentinel-init the min buffers (0x7F7F7F7F = 3.39e38).
    void* pA = nullptr; void* pB = nullptr;
    cudaGetSymbolAddress(&pA, g_minA);
    cudaGetSymbolAddress(&pB, g_minB);
    cudaMemsetAsync(pA, 0x7F, (size_t)NP * sizeof(float), 0);
    cudaMemsetAsync(pB, 0x7F, (size_t)NG * sizeof(float), 0);

    dim3 grid((NP + ROWS_BLK - 1) / ROWS_BLK, YCHUNKS, 1);
    pass_kernel<<<grid, TPB>>>(P, G, NP, NG);

    finalize1_kernel<<<FIN_BLKS, 256>>>(NP, NG);
    finalize2_kernel<<<1, 32>>>(out);
}

// round 8
// speedup vs baseline: 2.0084x; 2.0084x over previous
#include <cuda_runtime.h>

#define NMAX      16384
#define TPB       256
#define RPT       8                    // rows per thread
#define ROWS_BLK  (TPB * RPT)          // 2048 rows per block
#define TILE      128                  // columns per block (single tile)
#define FIN_BLKS  64

// Min buffers hold order-preserving uint keys (memset 0xFF = +max sentinel).
__device__ unsigned g_minA[NMAX];  // per pred row i: key(min_j (c_j - x_i.y_j))  [t-space]
__device__ unsigned g_minB[NMAX];  // per gt  col j: key(min_i 0.5*d2(i,j))
__device__ float    g_part[FIN_BLKS];

__device__ __forceinline__ float inf_f() { return __int_as_float(0x7f800000); }

// Monotone float->uint key: u = i ^ ((i>>31) | 0x80000000). min(u) == min(f).
__device__ __forceinline__ unsigned fkey(float v) {
    int i = __float_as_int(v);
    return (unsigned)i ^ ((unsigned)(i >> 31) | 0x80000000u);
}
// Inverse map.
__device__ __forceinline__ float funkey(unsigned u) {
    unsigned m = (~(unsigned)((int)u >> 31)) | 0x80000000u;
    return __int_as_float((int)(u ^ m));
}

// Warp-wide u32 min in one instruction (sm_80+, SASS REDUX).
__device__ __forceinline__ unsigned redux_min_u32(unsigned v) {
    unsigned r;
    asm("redux.sync.min.u32 %0, %1, 0xffffffff;" : "=r"(r) : "r"(v));
    return r;
}

// Fused single sweep. Block = 2048 rows x 128 cols.
//   t_ij = c_j - x_i.y_j           (3 FFMA chained from y.w; rowmin path)
//   u_ij = t_ij + h_i = 0.5*d2     (colmin path)
// Colmin per j: 8-row register tree -> key -> redux.min.u32 -> lane0 STS
// (warp-indexed, no atomics) -> tile-end fold -> global atomicMin(u32).
__global__ void __launch_bounds__(TPB, 3)
pass_kernel(const float* __restrict__ P, const float* __restrict__ G,
            int NP, int NG) {
    __shared__ float4   sy[TILE];
    __shared__ unsigned swm[TILE * 8];   // per-warp column min keys

    const int tid  = threadIdx.x;
    const int lane = tid & 31;
    const int wrp  = tid >> 5;
    const int row0 = blockIdx.x * ROWS_BLK + tid;
    const int yb   = blockIdx.y * TILE;

    float nx0[RPT], nx1[RPT], nx2[RPT], h[RPT], rowmin[RPT];
#pragma unroll
    for (int p = 0; p < RPT; p++) {
        int r = row0 + p * TPB;
        if (r < NP) {
            float a = P[3*r], b = P[3*r+1], c = P[3*r+2];
            nx0[p] = -a; nx1[p] = -b; nx2[p] = -c;
            h[p] = 0.5f * (a*a + b*b + c*c);
        } else {
            nx0[p] = 0.f; nx1[p] = 0.f; nx2[p] = 0.f;
            h[p] = inf_f();              // u = t + INF -> never wins colmin
        }
        rowmin[p] = inf_f();
    }

    for (int j = tid; j < TILE; j += TPB) {
        int g = yb + j;
        float4 v;
        if (g < NG) {
            float a = G[3*g], b = G[3*g+1], c = G[3*g+2];
            v = make_float4(a, b, c, 0.5f * (a*a + b*b + c*c));
        } else {
            v = make_float4(0.f, 0.f, 0.f, inf_f());  // t=+INF: inert both ways
        }
        sy[j] = v;
    }
    __syncthreads();

#pragma unroll 4
    for (int j = 0; j < TILE; j++) {
        const float4 y = sy[j];                  // one LDS.128 broadcast
        float cm;
#pragma unroll
        for (int p = 0; p < RPT; p++) {
            float t = fmaf(nx2[p], y.z, y.w);    // c_j - x.y
            t = fmaf(nx1[p], y.y, t);
            t = fmaf(nx0[p], y.x, t);
            rowmin[p] = fminf(rowmin[p], t);     // t-space rowmin
            float u = t + h[p];                  // 0.5*d2
            cm = p ? fminf(cm, u) : u;
        }
        unsigned k = redux_min_u32(fkey(cm));
        if (lane == 0) swm[j * 8 + wrp] = k;     // plain STS, warp-indexed
    }
    __syncthreads();

    if (tid < TILE) {
        unsigned m = swm[tid * 8];
#pragma unroll
        for (int w = 1; w < 8; w++) m = min(m, swm[tid * 8 + w]);
        int g = yb + tid;
        if (g < NG) atomicMin(&g_minB[g], m);
    }

#pragma unroll
    for (int p = 0; p < RPT; p++) {
        int r = row0 + p * TPB;
        if (r < NP) atomicMin(&g_minA[r], fkey(rowmin[p]));
    }
}

// Stage 1: 64 blocks reduce both key arrays. g_minA is t-space:
// d2 = 2*unkey + ||x||^2; g_minB: d2 = 2*unkey.
__global__ void finalize1_kernel(const float* __restrict__ P, int NP, int NG) {
    __shared__ float ssum[32];
    const int tid = threadIdx.x;
    const int gid = blockIdx.x * blockDim.x + tid;
    const int stride = gridDim.x * blockDim.x;
    const float wP = 1.0f / (float)NP;
    const float wG = 1.0f / (float)NG;
    float acc = 0.f;

    for (int i = gid; i < NP; i += stride) {
        float a = P[3*i], b = P[3*i+1], c = P[3*i+2];
        float d2 = 2.0f * funkey(g_minA[i]) + (a*a + b*b + c*c);
        acc += sqrtf(fmaxf(d2, 0.f)) * wP;
    }
    for (int j = gid; j < NG; j += stride)
        acc += sqrtf(fmaxf(2.0f * funkey(g_minB[j]), 0.f)) * wG;

#pragma unroll
    for (int o = 16; o > 0; o >>= 1) acc += __shfl_down_sync(0xffffffffu, acc, o);
    if ((tid & 31) == 0) ssum[tid >> 5] = acc;
    __syncthreads();
    if (tid < 32) {
        int nwarps = blockDim.x >> 5;
        float v = (tid < nwarps) ? ssum[tid] : 0.f;
#pragma unroll
        for (int o = 16; o > 0; o >>= 1) v += __shfl_down_sync(0xffffffffu, v, o);
        if (tid == 0) g_part[blockIdx.x] = v;
    }
}

// Stage 2: one warp, fixed-order deterministic sum.
__global__ void finalize2_kernel(float* __restrict__ out) {
    const int tid = threadIdx.x;
    float v = (tid < FIN_BLKS) ? g_part[tid] : 0.f;
    if (tid + 32 < FIN_BLKS) v += g_part[tid + 32];
#pragma unroll
    for (int o = 16; o > 0; o >>= 1) v += __shfl_down_sync(0xffffffffu, v, o);
    if (tid == 0) out[0] = v;
}

extern "C" void kernel_launch(void* const* d_in, const int* in_sizes, int n_in,
                              void* d_out, int out_size) {
    const float* P = (const float*)d_in[0];
    const float* G = (const float*)d_in[1];
    const int NP = in_sizes[0] / 3;
    const int NG = in_sizes[1] / 3;
    float* out = (float*)d_out;

    // Key-space sentinel: 0xFFFFFFFF = max key.
    void* pA = nullptr; void* pB = nullptr;
    cudaGetSymbolAddress(&pA, g_minA);
    cudaGetSymbolAddress(&pB, g_minB);
    cudaMemsetAsync(pA, 0xFF, (size_t)NP * sizeof(unsigned), 0);
    cudaMemsetAsync(pB, 0xFF, (size_t)NG * sizeof(unsigned), 0);

    dim3 grid((NP + ROWS_BLK - 1) / ROWS_BLK, (NG + TILE - 1) / TILE, 1);
    pass_kernel<<<grid, TPB>>>(P, G, NP, NG);

    finalize1_kernel<<<FIN_BLKS, 512>>>(P, NP, NG);
    finalize2_kernel<<<1, 32>>>(out);
}

// round 9
// speedup vs baseline: 2.0708x; 1.0311x over previous
#include <cuda_runtime.h>

#define NMAX      16384
#define TPB       256
#define RPT       8                    // rows per thread
#define ROWS_BLK  (TPB * RPT)          // 2048 rows per block
#define TILE      128                  // columns per block (single tile)
#define FIN_BLKS  64

// Min buffers hold order-preserving uint keys (memset 0xFF = +max sentinel).
__device__ unsigned g_minA[NMAX];  // per pred row i: key(min_j (c_j - x_i.y_j))  [t-space]
__device__ unsigned g_minB[NMAX];  // per gt  col j: key(min_i 0.5*d2(i,j))
__device__ float    g_part[FIN_BLKS];

__device__ __forceinline__ float inf_f() { return __int_as_float(0x7f800000); }

// Monotone float->uint key: u = i ^ ((i>>31) | 0x80000000). min(u) == min(f).
__device__ __forceinline__ unsigned fkey(float v) {
    int i = __float_as_int(v);
    return (unsigned)i ^ ((unsigned)(i >> 31) | 0x80000000u);
}
// Inverse map.
__device__ __forceinline__ float funkey(unsigned u) {
    unsigned m = (~(unsigned)((int)u >> 31)) | 0x80000000u;
    return __int_as_float((int)(u ^ m));
}

// Warp-wide u32 min in one instruction (sm_80+, SASS REDUX).
__device__ __forceinline__ unsigned redux_min_u32(unsigned v) {
    unsigned r;
    asm("redux.sync.min.u32 %0, %1, 0xffffffff;" : "=r"(r) : "r"(v));
    return r;
}

// Fused single sweep. Block = 2048 rows x 128 cols.
//   t_ij = c_j - x_i.y_j           (3 FFMA chained from y.w; rowmin path)
//   u_ij = t_ij + h_i = 0.5*d2     (colmin path)
// Colmin per j: 8-row chain -> key -> redux.min.u32 -> lane0 STS (warp-
// indexed, no atomics) -> tile-end fold -> global atomicMin(u32).
__global__ void __launch_bounds__(TPB, 4)
pass_kernel(const float* __restrict__ P, const float* __restrict__ G,
            int NP, int NG) {
    __shared__ float4   sy[TILE];
    __shared__ unsigned swm[TILE * 8];   // per-warp column min keys

    const int tid  = threadIdx.x;
    const int lane = tid & 31;
    const int wrp  = tid >> 5;
    const int row0 = blockIdx.x * ROWS_BLK + tid;
    const int yb   = blockIdx.y * TILE;

    float nx0[RPT], nx1[RPT], nx2[RPT], h[RPT], rowmin[RPT];
#pragma unroll
    for (int p = 0; p < RPT; p++) {
        int r = row0 + p * TPB;
        if (r < NP) {
            float a = P[3*r], b = P[3*r+1], c = P[3*r+2];
            nx0[p] = -a; nx1[p] = -b; nx2[p] = -c;
            h[p] = 0.5f * (a*a + b*b + c*c);
        } else {
            nx0[p] = 0.f; nx1[p] = 0.f; nx2[p] = 0.f;
            h[p] = inf_f();              // u = t + INF -> never wins colmin
        }
        rowmin[p] = inf_f();
    }

    for (int j = tid; j < TILE; j += TPB) {
        int g = yb + j;
        float4 v;
        if (g < NG) {
            float a = G[3*g], b = G[3*g+1], c = G[3*g+2];
            v = make_float4(a, b, c, 0.5f * (a*a + b*b + c*c));
        } else {
            v = make_float4(0.f, 0.f, 0.f, inf_f());  // t=+INF: inert both ways
        }
        sy[j] = v;
    }
    __syncthreads();

#pragma unroll 2
    for (int j = 0; j < TILE; j++) {
        const float4 y = sy[j];                  // one LDS.128 broadcast
        float cm;
#pragma unroll
        for (int p = 0; p < RPT; p++) {
            float t = fmaf(nx2[p], y.z, y.w);    // c_j - x.y
            t = fmaf(nx1[p], y.y, t);
            t = fmaf(nx0[p], y.x, t);
            rowmin[p] = fminf(rowmin[p], t);     // t-space rowmin
            float u = t + h[p];                  // 0.5*d2
            cm = p ? fminf(cm, u) : u;
        }
        unsigned k = redux_min_u32(fkey(cm));
        if (lane == 0) swm[j * 8 + wrp] = k;     // plain STS, warp-indexed
    }
    __syncthreads();

    if (tid < TILE) {
        unsigned m = swm[tid * 8];
#pragma unroll
        for (int w = 1; w < 8; w++) m = min(m, swm[tid * 8 + w]);
        int g = yb + tid;
        if (g < NG) atomicMin(&g_minB[g], m);
    }

#pragma unroll
    for (int p = 0; p < RPT; p++) {
        int r = row0 + p * TPB;
        if (r < NP) atomicMin(&g_minA[r], fkey(rowmin[p]));
    }
}

// Stage 1: 64 blocks reduce both key arrays. g_minA is t-space:
// d2 = 2*unkey + ||x||^2; g_minB: d2 = 2*unkey.
__global__ void finalize1_kernel(const float* __restrict__ P, int NP, int NG) {
    __shared__ float ssum[32];
    const int tid = threadIdx.x;
    const int gid = blockIdx.x * blockDim.x + tid;
    const int stride = gridDim.x * blockDim.x;
    const float wP = 1.0f / (float)NP;
    const float wG = 1.0f / (float)NG;
    float acc = 0.f;

    for (int i = gid; i < NP; i += stride) {
        float a = P[3*i], b = P[3*i+1], c = P[3*i+2];
        float d2 = 2.0f * funkey(g_minA[i]) + (a*a + b*b + c*c);
        acc += sqrtf(fmaxf(d2, 0.f)) * wP;
    }
    for (int j = gid; j < NG; j += stride)
        acc += sqrtf(fmaxf(2.0f * funkey(g_minB[j]), 0.f)) * wG;

#pragma unroll
    for (int o = 16; o > 0; o >>= 1) acc += __shfl_down_sync(0xffffffffu, acc, o);
    if ((tid & 31) == 0) ssum[tid >> 5] = acc;
    __syncthreads();
    if (tid < 32) {
        int nwarps = blockDim.x >> 5;
        float v = (tid < nwarps) ? ssum[tid] : 0.f;
#pragma unroll
        for (int o = 16; o > 0; o >>= 1) v += __shfl_down_sync(0xffffffffu, v, o);
        if (tid == 0) g_part[blockIdx.x] = v;
    }
}

// Stage 2: one warp, fixed-order deterministic sum.
__global__ void finalize2_kernel(float* __restrict__ out) {
    const int tid = threadIdx.x;
    float v = (tid < FIN_BLKS) ? g_part[tid] : 0.f;
    if (tid + 32 < FIN_BLKS) v += g_part[tid + 32];
#pragma unroll
    for (int o = 16; o > 0; o >>= 1) v += __shfl_down_sync(0xffffffffu, v, o);
    if (tid == 0) out[0] = v;
}

extern "C" void kernel_launch(void* const* d_in, const int* in_sizes, int n_in,
                              void* d_out, int out_size) {
    const float* P = (const float*)d_in[0];
    const float* G = (const float*)d_in[1];
    const int NP = in_sizes[0] / 3;
    const int NG = in_sizes[1] / 3;
    float* out = (float*)d_out;

    // Key-space sentinel: 0xFFFFFFFF = max key.
    void* pA = nullptr; void* pB = nullptr;
    cudaGetSymbolAddress(&pA, g_minA);
    cudaGetSymbolAddress(&pB, g_minB);
    cudaMemsetAsync(pA, 0xFF, (size_t)NP * sizeof(unsigned), 0);
    cudaMemsetAsync(pB, 0xFF, (size_t)NG * sizeof(unsigned), 0);

    dim3 grid((NP + ROWS_BLK - 1) / ROWS_BLK, (NG + TILE - 1) / TILE, 1);
    pass_kernel<<<grid, TPB>>>(P, G, NP, NG);

    finalize1_kernel<<<FIN_BLKS, 512>>>(P, NP, NG);
    finalize2_kernel<<<1, 32>>>(out);
}